// round 15
// baseline (speedup 1.0000x reference)
#include <cuda_runtime.h>
#include <cstdint>

// Problem constants
#define WIDTH      1000
#define HEIGHT     1000
#define PATCH      5
#define PPW        (WIDTH / PATCH)        // 200 patches per patch-row (band)
#define NUM_TERMS  10
#define NPIX       (WIDTH * HEIGHT)       // 1,000,000
#define NBANDS     (HEIGHT / PATCH)       // 200 bands
#define SEGS       8                      // segments per band
#define PPB        (PPW / SEGS)           // 25 patches per block
#define CPB        (PPB * PATCH)          // 125 columns (pixels) per block row
#define THREADS    128
#define CPP        60                     // coefficient floats per patch

// Block: tile of 25 patches (125 cols x 5 rows). All global traffic coalesced.
// Coefficients stored TRANSPOSED in smem: s_coefT[i*25 + q] so that the
// stage-2 read (lane-fast q) has lane stride 1 word -> bank-conflict-free.
__global__ void __launch_bounds__(THREADS, 10)
ts_approx_kernel(const float* __restrict__ pix,     // [NPIX, 2]
                 const float* __restrict__ coef,    // [NPATCH, 3, 10, 2]
                 const float* __restrict__ bias,    // [NPATCH, 3]
                 float* __restrict__ out)           // [3, NPIX]
{
    __shared__ float  s_coefT[CPP * PPB];       // [60][25] transposed (6000 B)
    __shared__ float2 s_pix[PATCH * CPB];       // 5 rows * 125 float2  (5000 B)
    __shared__ float  s_biasT[3 * PPB];         // [3][25] transposed    (300 B)
    __shared__ float  s_out[3 * PATCH * CPB];   // 3ch * 5 rows * 125   (7500 B)

    const int tid  = threadIdx.x;
    const int band = blockIdx.y;          // [0, 200)
    const int seg  = blockIdx.x;          // [0, 8)
    const int P0   = band * PPW + seg * PPB;        // first patch id
    const int col0 = seg * CPB;                     // first pixel column
    const int row0 = band * PATCH;                  // first pixel row

    // ---- Stage 1: coalesced loads, transposing coef/bias into smem ----
    {
        // 1500 floats of coefficients; gmem read coalesced, smem write
        // lane-stride 25 words (gcd(25,32)=1 -> conflict-free).
        const float* csrc = coef + (size_t)P0 * CPP;
#pragma unroll
        for (int idx = tid; idx < PPB * CPP; idx += THREADS) {
            const float v = __ldg(csrc + idx);
            const int q = idx / CPP;
            const int i = idx - q * CPP;
            s_coefT[i * PPB + q] = v;
        }

        const float2* psrc = reinterpret_cast<const float2*>(pix);
#pragma unroll
        for (int r = 0; r < PATCH; r++)
            if (tid < CPB)
                s_pix[r * CPB + tid] = __ldg(psrc + (size_t)(row0 + r) * WIDTH + col0 + tid);

        if (tid < PPB * 3) {
            const int q  = tid / 3;
            const int ch = tid - q * 3;
            s_biasT[ch * PPB + q] = __ldg(bias + P0 * 3 + tid);
        }
    }
    __syncthreads();

    // ---- Stage 2: compute (125 active threads; q fastest across lanes) ----
    if (tid < PPB * PATCH) {
        const int q = tid % PPB;          // [0, 25)  patch-in-block (lane-fast)
        const int r = tid / PPB;          // [0, 5)   row-in-patch

        float x[PATCH], y[PATCH];
#pragma unroll
        for (int j = 0; j < PATCH; j++) {
            const float2 p = s_pix[r * CPB + q * PATCH + j];
            x[j] = p.x; y[j] = p.y;
        }

#pragma unroll
        for (int ch = 0; ch < 3; ch++) {
            // Hoist this channel's 20 coefficients to registers
            // (lane stride 1 word in smem -> conflict-free LDS).
            float c[20];
#pragma unroll
            for (int i = 0; i < 20; i++)
                c[i] = s_coefT[(ch * 20 + i) * PPB + q];
            const float b = s_biasT[ch * PPB + q];

#pragma unroll
            for (int j = 0; j < PATCH; j++) {
                float hx = c[18];   // t=9 x-coef
                float hy = c[19];   // t=9 y-coef
#pragma unroll
                for (int t = 8; t >= 0; t--) {
                    hx = fmaf(hx, x[j], c[2 * t + 0]);
                    hy = fmaf(hy, y[j], c[2 * t + 1]);
                }
                // lane stride 5 words, gcd(5,32)=1 -> conflict-free STS
                s_out[(ch * PATCH + r) * CPB + q * PATCH + j] = (hx + hy) + b;
            }
        }
    }
    __syncthreads();

    // ---- Stage 3: coalesced flush (15 contiguous 125-float segments) ----
    if (tid < CPB) {
#pragma unroll
        for (int ch = 0; ch < 3; ch++)
#pragma unroll
            for (int r = 0; r < PATCH; r++)
                out[(size_t)ch * NPIX + (size_t)(row0 + r) * WIDTH + col0 + tid] =
                    s_out[(ch * PATCH + r) * CPB + tid];
    }
}

extern "C" void kernel_launch(void* const* d_in, const int* in_sizes, int n_in,
                              void* d_out, int out_size)
{
    const float* pix  = (const float*)d_in[0];   // [1e6, 2]
    const float* coef = (const float*)d_in[1];   // [40000, 3, 10, 2]
    const float* bias = (const float*)d_in[2];   // [40000, 3]
    float* out = (float*)d_out;                  // [3, 1e6]

    dim3 grid(SEGS, NBANDS);                     // 8 x 200 = 1600 blocks
    ts_approx_kernel<<<grid, THREADS>>>(pix, coef, bias, out);
}

// round 17
// speedup vs baseline: 1.0025x; 1.0025x over previous
#include <cuda_runtime.h>
#include <cstdint>

// Problem constants
#define WIDTH      1000
#define HEIGHT     1000
#define PATCH      5
#define PPW        (WIDTH / PATCH)        // 200 patches per patch-row (band)
#define NUM_TERMS  10
#define NPIX       (WIDTH * HEIGHT)       // 1,000,000
#define NBANDS     (HEIGHT / PATCH)       // 200 bands
#define SEGS       8                      // segments per band
#define PPB        (PPW / SEGS)           // 25 patches per block
#define CPB        (PPB * PATCH)          // 125 columns (pixels) per block row
#define THREADS    128

// R9 structure (measured best, 9.95us kernel) minus the s_out round-trip:
// - float4 coefficient staging (vectorized LDG.128 + LDS.128; the 8-lane
//   phase pattern of LDS.128 at q-stride 60 words is conflict-free)
// - compute threads store results DIRECTLY to gmem (15 STG.32/thread),
//   removing 15 STS + 15 LDS + one __syncthreads per thread and 7.5KB smem.
__global__ void __launch_bounds__(THREADS, 10)
ts_approx_kernel(const float* __restrict__ pix,     // [NPIX, 2]
                 const float* __restrict__ coef,    // [NPATCH, 3, 10, 2]
                 const float* __restrict__ bias,    // [NPATCH, 3]
                 float* __restrict__ out)           // [3, NPIX]
{
    __shared__ float4 s_coef4[PPB * 15];        // 25 patches * 60 floats (6000 B)
    __shared__ float2 s_pix[PATCH * CPB];       // 5 rows * 125 float2   (5000 B)
    __shared__ float  s_bias[PPB * 3];          //                        (300 B)

    const int tid  = threadIdx.x;
    const int band = blockIdx.y;          // [0, 200)
    const int seg  = blockIdx.x;          // [0, 8)
    const int P0   = band * PPW + seg * PPB;        // first patch id
    const int col0 = seg * CPB;                     // first pixel column
    const int row0 = band * PATCH;                  // first pixel row

    // ---- Stage 1: coalesced cooperative loads into smem ----
    {
        const float4* csrc = reinterpret_cast<const float4*>(coef + (size_t)P0 * 60);
#pragma unroll
        for (int i = tid; i < PPB * 15; i += THREADS)   // 375 float4s
            s_coef4[i] = __ldg(csrc + i);

        const float2* psrc = reinterpret_cast<const float2*>(pix);
#pragma unroll
        for (int r = 0; r < PATCH; r++)
            if (tid < CPB)
                s_pix[r * CPB + tid] = __ldg(psrc + (size_t)(row0 + r) * WIDTH + col0 + tid);

        if (tid < PPB * 3)
            s_bias[tid] = __ldg(bias + P0 * 3 + tid);
    }
    __syncthreads();

    // ---- Stage 2: compute + direct global stores ----
    if (tid < PPB * PATCH) {
        const int q = tid % PPB;          // [0, 25)  patch-in-block (lane-fast)
        const int r = tid / PPB;          // [0, 5)   row-in-patch

        float x[PATCH], y[PATCH];
#pragma unroll
        for (int j = 0; j < PATCH; j++) {
            const float2 p = s_pix[r * CPB + q * PATCH + j];
            x[j] = p.x; y[j] = p.y;
        }

        const float* cpat = reinterpret_cast<const float*>(s_coef4 + q * 15);
        // this thread's output base: channel 0, row row0+r, cols col0+q*5..+4
        float* obase = out + (size_t)(row0 + r) * WIDTH + col0 + q * PATCH;

#pragma unroll
        for (int ch = 0; ch < 3; ch++) {
            const float* c = cpat + ch * 20;   // c[2t]=x-coef, c[2t+1]=y-coef
            const float  b = s_bias[q * 3 + ch];
            float* o = obase + (size_t)ch * NPIX;
#pragma unroll
            for (int j = 0; j < PATCH; j++) {
                float hx = c[18];   // t=9 x-coef
                float hy = c[19];   // t=9 y-coef
#pragma unroll
                for (int t = 8; t >= 0; t--) {
                    hx = fmaf(hx, x[j], c[2 * t + 0]);
                    hy = fmaf(hy, y[j], c[2 * t + 1]);
                }
                o[j] = (hx + hy) + b;
            }
        }
    }
}

extern "C" void kernel_launch(void* const* d_in, const int* in_sizes, int n_in,
                              void* d_out, int out_size)
{
    const float* pix  = (const float*)d_in[0];   // [1e6, 2]
    const float* coef = (const float*)d_in[1];   // [40000, 3, 10, 2]
    const float* bias = (const float*)d_in[2];   // [40000, 3]
    float* out = (float*)d_out;                  // [3, 1e6]

    dim3 grid(SEGS, NBANDS);                     // 8 x 200 = 1600 blocks
    ts_approx_kernel<<<grid, THREADS>>>(pix, coef, bias, out);
}